// round 2
// baseline (speedup 1.0000x reference)
#include <cuda_runtime.h>
#include <cuda_bf16.h>
#include <math.h>

#define HIDDEN 3584
#define NQ 28
#define NKV 4
#define HD 128
#define SEQ 2048
#define BATCH 2
#define NREP (NQ / NKV)

// ---------------- scratch (static device allocations; no cudaMalloc) --------
__device__ float g_tmp[BATCH * SEQ * HIDDEN];        // plain GEMM out / context
__device__ float g_q[BATCH * NQ * SEQ * HD];         // [B,Hq,S,D]
__device__ float g_k[BATCH * NKV * SEQ * HD];        // [B,Hkv,S,D]
__device__ float g_v[BATCH * NKV * SEQ * HD];        // [B,Hkv,S,D]

// ---------------- SGEMM: C[m,n] = sum_k A[m,k] * W[n,k] (+bias[n]) ----------
#define BM 128
#define BN 128
#define BK 8

__global__ __launch_bounds__(256) void sgemm_bias(
    const float* __restrict__ A, const float* __restrict__ W,
    const float* __restrict__ bias, float* __restrict__ C,
    int M, int N, int K)
{
    __shared__ float As[BK][BM];
    __shared__ float Bs[BK][BN];

    const int t  = threadIdx.x;
    const int m0 = blockIdx.y * BM;
    const int n0 = blockIdx.x * BN;

    const int lr = t >> 1;            // 0..127
    const int lk = (t & 1) * 4;       // 0 or 4

    const float* Ap = A + (size_t)(m0 + lr) * K + lk;
    const float* Wp = W + (size_t)(n0 + lr) * K + lk;

    const int tx = t % 16;            // n micro
    const int ty = t / 16;            // m micro

    float acc[8][8];
#pragma unroll
    for (int i = 0; i < 8; i++)
#pragma unroll
        for (int j = 0; j < 8; j++) acc[i][j] = 0.f;

    for (int k0 = 0; k0 < K; k0 += BK) {
        float4 av = *(const float4*)(Ap + k0);
        float4 wv = *(const float4*)(Wp + k0);
        As[lk + 0][lr] = av.x; As[lk + 1][lr] = av.y;
        As[lk + 2][lr] = av.z; As[lk + 3][lr] = av.w;
        Bs[lk + 0][lr] = wv.x; Bs[lk + 1][lr] = wv.y;
        Bs[lk + 2][lr] = wv.z; Bs[lk + 3][lr] = wv.w;
        __syncthreads();

#pragma unroll
        for (int kk = 0; kk < BK; kk++) {
            float4 a0 = *(const float4*)&As[kk][ty * 8];
            float4 a1 = *(const float4*)&As[kk][ty * 8 + 4];
            float4 b0 = *(const float4*)&Bs[kk][tx * 8];
            float4 b1 = *(const float4*)&Bs[kk][tx * 8 + 4];
            float a[8] = {a0.x, a0.y, a0.z, a0.w, a1.x, a1.y, a1.z, a1.w};
            float b[8] = {b0.x, b0.y, b0.z, b0.w, b1.x, b1.y, b1.z, b1.w};
#pragma unroll
            for (int i = 0; i < 8; i++)
#pragma unroll
                for (int j = 0; j < 8; j++) acc[i][j] += a[i] * b[j];
        }
        __syncthreads();
    }

    float bb[8];
#pragma unroll
    for (int j = 0; j < 8; j++)
        bb[j] = bias ? bias[n0 + tx * 8 + j] : 0.f;

#pragma unroll
    for (int i = 0; i < 8; i++) {
        int m = m0 + ty * 8 + i;
        float* Crow = C + (size_t)m * N + n0 + tx * 8;
        float4 v0, v1;
        v0.x = acc[i][0] + bb[0]; v0.y = acc[i][1] + bb[1];
        v0.z = acc[i][2] + bb[2]; v0.w = acc[i][3] + bb[3];
        v1.x = acc[i][4] + bb[4]; v1.y = acc[i][5] + bb[5];
        v1.z = acc[i][6] + bb[6]; v1.w = acc[i][7] + bb[7];
        *(float4*)(Crow)     = v0;
        *(float4*)(Crow + 4) = v1;
    }
}

// ---------------- robust position decode (int64 / int32 / float32) ----------
// position_ids is arange(S); first words disambiguate the stored dtype:
//   int64  : words [0,0,1,0,...]
//   int32  : words [0,1,2,3,...]
//   float32: words [0, 0x3F800000, ...]
__device__ __forceinline__ float get_pos(const void* pos, int s)
{
    const int* p32 = (const int*)pos;
    if (p32[2] == 1 && p32[3] == 0) {                 // int64
        return (float)((const long long*)pos)[s];
    } else if (p32[1] == 1 && p32[2] == 2) {          // int32
        return (float)p32[s];
    } else {                                          // float32
        return ((const float*)pos)[s];
    }
}

// ---------------- RoPE + transpose:  [B,S,H,D] -> [B,H,S,D] -----------------
__global__ void rope_kernel(const float* __restrict__ in, float* __restrict__ out,
                            const void* __restrict__ pos, int H, int total)
{
    int idx = blockIdx.x * blockDim.x + threadIdx.x;
    if (idx >= total) return;          // total = B*H*S*64
    int per = idx;
    int d = per & 63;     per >>= 6;
    int s = per & (SEQ - 1); per /= SEQ;
    int h = per % H;
    int b = per / H;

    size_t ibase = (((size_t)b * SEQ + s) * H + h) * HD;
    float x1 = in[ibase + d];
    float x2 = in[ibase + d + 64];

    float inv = powf(1000000.0f, -(float)d / 64.0f);
    float ang = get_pos(pos, s) * inv;
    float sn, cs;
    sincosf(ang, &sn, &cs);

    size_t obase = (((size_t)b * H + h) * SEQ + s) * HD;
    out[obase + d]      = x1 * cs - x2 * sn;
    out[obase + d + 64] = x2 * cs + x1 * sn;
}

// ---------------- plain transpose for V: [B,S,H,D] -> [B,H,S,D] -------------
__global__ void vtrans_kernel(const float* __restrict__ in, float* __restrict__ out,
                              int total)
{
    int idx = blockIdx.x * blockDim.x + threadIdx.x;
    if (idx >= total) return;          // total = B*NKV*SEQ*HD
    int per = idx;
    int d = per & (HD - 1);  per >>= 7;
    int s = per & (SEQ - 1); per /= SEQ;
    int h = per % NKV;
    int b = per / NKV;
    out[idx] = in[(((size_t)b * SEQ + s) * NKV + h) * HD + d];
}

// ---------------- flash attention (fp32), output in [B,S,Hq*D] --------------
#define AQ 64
#define AK 32
#define QSCALE 0.08838834764831845f   // 1/sqrt(128)

__global__ __launch_bounds__(256, 2) void attn_kernel(
    const float* __restrict__ Qg, const float* __restrict__ Kg,
    const float* __restrict__ Vg, const float* __restrict__ maskg,
    float* __restrict__ Out)
{
    __shared__ float Ks[AK * HD];
    __shared__ float Vs[AK * HD];
    __shared__ float Ms[AQ * AK];

    const int t   = threadIdx.x;
    const int row = t >> 2;       // 0..63 (query row within tile)
    const int p   = t & 3;        // d-slice 0..3 (32 dims each)
    const int qt  = blockIdx.x;
    const int h   = blockIdx.y;
    const int b   = blockIdx.z;
    const int hkv = h / NREP;
    const int qr  = qt * AQ + row;

    const float* Qrow = Qg + (((size_t)(b * NQ + h) * SEQ) + qr) * HD + p * 32;
    float q[32];
#pragma unroll
    for (int i = 0; i < 32; i += 4) {
        float4 v4 = *(const float4*)(Qrow + i);
        q[i]     = v4.x * QSCALE;
        q[i + 1] = v4.y * QSCALE;
        q[i + 2] = v4.z * QSCALE;
        q[i + 3] = v4.w * QSCALE;
    }

    float o[32];
#pragma unroll
    for (int i = 0; i < 32; i++) o[i] = 0.f;
    float mcur = -INFINITY, l = 0.f;

    const float* Kbase = Kg + (size_t)(b * NKV + hkv) * SEQ * HD;
    const float* Vbase = Vg + (size_t)(b * NKV + hkv) * SEQ * HD;
    const float* Mbase = maskg + ((size_t)b * SEQ + (size_t)qt * AQ) * SEQ;

    for (int k0 = 0; k0 < SEQ; k0 += AK) {
        const float* ks = Kbase + (size_t)k0 * HD;
        const float* vs = Vbase + (size_t)k0 * HD;
#pragma unroll
        for (int i = 0; i < 4; i++) {
            int idx = (i * 256 + t) * 4;
            *(float4*)(Ks + idx) = *(const float4*)(ks + idx);
            *(float4*)(Vs + idx) = *(const float4*)(vs + idx);
        }
#pragma unroll
        for (int i = 0; i < 2; i++) {
            int idx = (i * 256 + t) * 4;     // 0..2047
            int r = idx >> 5, c = idx & 31;
            *(float4*)(Ms + idx) = *(const float4*)(Mbase + (size_t)r * SEQ + k0 + c);
        }
        __syncthreads();

        float s[AK];
#pragma unroll
        for (int j = 0; j < AK; j++) {
            const float4* kr = (const float4*)(Ks + j * HD + p * 32);
            float acc = 0.f;
#pragma unroll
            for (int i4 = 0; i4 < 8; i4++) {
                float4 kv = kr[i4];
                acc += q[4 * i4]     * kv.x;
                acc += q[4 * i4 + 1] * kv.y;
                acc += q[4 * i4 + 2] * kv.z;
                acc += q[4 * i4 + 3] * kv.w;
            }
            s[j] = acc;
        }
#pragma unroll
        for (int j = 0; j < AK; j++) {
            s[j] += __shfl_xor_sync(0xffffffffu, s[j], 1);
            s[j] += __shfl_xor_sync(0xffffffffu, s[j], 2);
            s[j] += Ms[row * AK + j];
        }

        float mt = mcur;
#pragma unroll
        for (int j = 0; j < AK; j++) mt = fmaxf(mt, s[j]);
        float corr = __expf(mcur - mt);
        mcur = mt;
        l *= corr;
#pragma unroll
        for (int i = 0; i < 32; i++) o[i] *= corr;

#pragma unroll
        for (int j = 0; j < AK; j++) {
            float pj = __expf(s[j] - mcur);
            l += pj;
            const float4* vr = (const float4*)(Vs + j * HD + p * 32);
#pragma unroll
            for (int i4 = 0; i4 < 8; i4++) {
                float4 vv = vr[i4];
                o[4 * i4]     += pj * vv.x;
                o[4 * i4 + 1] += pj * vv.y;
                o[4 * i4 + 2] += pj * vv.z;
                o[4 * i4 + 3] += pj * vv.w;
            }
        }
        __syncthreads();
    }

    float inv = 1.f / l;
    float* orow = Out + ((size_t)b * SEQ + qr) * (NQ * HD) + h * HD + p * 32;
#pragma unroll
    for (int i = 0; i < 32; i += 4) {
        float4 v4;
        v4.x = o[i] * inv; v4.y = o[i + 1] * inv;
        v4.z = o[i + 2] * inv; v4.w = o[i + 3] * inv;
        *(float4*)(orow + i) = v4;
    }
}

// ---------------- launcher ---------------------------------------------------
extern "C" void kernel_launch(void* const* d_in, const int* in_sizes, int n_in,
                              void* d_out, int out_size)
{
    const float* X    = (const float*)d_in[0];   // [B,S,HIDDEN]
    const float* mask = (const float*)d_in[1];   // [B,1,S,S]
    const void*  pos  = (const void*)d_in[2];    // dtype sniffed in-kernel
    const float* wq   = (const float*)d_in[3];
    const float* bq   = (const float*)d_in[4];
    const float* wk   = (const float*)d_in[5];
    const float* bk   = (const float*)d_in[6];
    const float* wv   = (const float*)d_in[7];
    const float* bv   = (const float*)d_in[8];
    const float* wo   = (const float*)d_in[9];
    float*       out  = (float*)d_out;

    float *tmp, *qb, *kb, *vb;
    cudaGetSymbolAddress((void**)&tmp, g_tmp);
    cudaGetSymbolAddress((void**)&qb,  g_q);
    cudaGetSymbolAddress((void**)&kb,  g_k);
    cudaGetSymbolAddress((void**)&vb,  g_v);

    const int M = BATCH * SEQ;   // 4096

    // Q projection + RoPE
    {
        dim3 grid((NQ * HD) / BN, M / BM);
        sgemm_bias<<<grid, 256>>>(X, wq, bq, tmp, M, NQ * HD, HIDDEN);
        int total = BATCH * NQ * SEQ * 64;
        rope_kernel<<<(total + 255) / 256, 256>>>(tmp, qb, pos, NQ, total);
    }
    // K projection + RoPE
    {
        dim3 grid((NKV * HD) / BN, M / BM);
        sgemm_bias<<<grid, 256>>>(X, wk, bk, tmp, M, NKV * HD, HIDDEN);
        int total = BATCH * NKV * SEQ * 64;
        rope_kernel<<<(total + 255) / 256, 256>>>(tmp, kb, pos, NKV, total);
    }
    // V projection + transpose
    {
        dim3 grid((NKV * HD) / BN, M / BM);
        sgemm_bias<<<grid, 256>>>(X, wv, bv, tmp, M, NKV * HD, HIDDEN);
        int total = BATCH * NKV * SEQ * HD;
        vtrans_kernel<<<(total + 255) / 256, 256>>>(tmp, vb, total);
    }
    // attention -> context in [B,S,Hq*D] (stored into tmp)
    {
        dim3 grid(SEQ / AQ, NQ, BATCH);
        attn_kernel<<<grid, 256>>>(qb, kb, vb, mask, tmp);
    }
    // output projection (no bias)
    {
        dim3 grid(HIDDEN / BN, M / BM);
        sgemm_bias<<<grid, 256>>>(tmp, wo, nullptr, out, M, HIDDEN, HIDDEN);
    }
}